// round 7
// baseline (speedup 1.0000x reference)
#include <cuda_runtime.h>
#include <cuda_bf16.h>
#include <math.h>
#include <stdint.h>

#define N_NODES 8192
#define D 64
#define NT 8192
#define KC 192            // packed K: [hi | lo | hi] / [hi | hi | lo]
#define EMAX 262144

// ---------------- scratch (no allocations allowed) ----------------
// Invariant: g_deg and g_agg are ZERO at entry to kernel_launch (zero-initialized
// at module load; re-zeroed by the GEMM's idle lower-triangle CTAs each call).
__device__ float g_deg[N_NODES];
__device__ float g_h[N_NODES * D];     // x @ W
__device__ float g_agg[N_NODES * D];   // neighbor-sum (excl. self term)
__device__ __nv_bfloat16 g_A2[N_NODES * KC];
__device__ __nv_bfloat16 g_B2[N_NODES * KC];

struct Cls {
    const float* x;
    const void*  ei;
    const float* W;
    const float* b;
    int E;
    int ei32;
};

__device__ __forceinline__ bool range_ok_i64(const long long* p, int n) {
    int stride = n / 64; if (stride < 1) stride = 1;
    for (int k = 0; k < 64; k++) {
        long long v = p[(long long)k * stride];
        if (v < 0 || v >= N_NODES) return false;
    }
    return true;
}
__device__ __forceinline__ bool range_ok_i32(const int* p, int n) {
    int stride = n / 64; if (stride < 1) stride = 1;
    for (int k = 0; k < 64; k++) {
        int v = p[k * stride];
        if (v < 0 || v >= N_NODES) return false;
    }
    return true;
}

// Per-block self-classification (uniform result; reads are L2-resident).
__device__ Cls do_classify(const void* p0, const void* p1, const void* p2, const void* p3,
                           int s0, int s1, int s2, int s3) {
    Cls c; c.x = nullptr; c.ei = nullptr; c.W = nullptr; c.b = nullptr; c.E = 0; c.ei32 = 1;
    const void* ps[4] = {p0, p1, p2, p3};
    int ss[4] = {s0, s1, s2, s3};
    int big[2]; int nb = 0;
    for (int j = 0; j < 4; j++) {
        if (ss[j] == D) c.b = (const float*)ps[j];
        else if (ss[j] == D * D) c.W = (const float*)ps[j];
        else if (nb < 2) big[nb++] = j;
    }
    for (int k = 0; k < 2; k++) {
        const void* cand = ps[big[k]];
        int n = ss[big[k]];
        const void* other = ps[big[1 - k]];
        if (range_ok_i64((const long long*)cand, n)) {
            c.ei = cand; c.ei32 = 0; c.E = n / 2; c.x = (const float*)other; return c;
        }
        if (range_ok_i32((const int*)cand, n)) {
            c.ei = cand; c.ei32 = 1; c.E = n / 2; c.x = (const float*)other; return c;
        }
    }
    c.ei = ps[big[1]]; c.ei32 = 1; c.E = ss[big[1]] / 2;
    c.x = (const float*)ps[big[0]];
    return c;
}

__device__ __forceinline__ int fetch_idx(const void* ei, int i, int ei32) {
    if (ei32) return ((const int*)ei)[i];
    return (int)((const long long*)ei)[i];
}

__device__ __forceinline__ uint32_t smem_u32(const void* p) {
    uint32_t a;
    asm("{ .reg .u64 t; cvta.to.shared.u64 t, %1; cvt.u32.u64 %0, t; }" : "=r"(a) : "l"(p));
    return a;
}

// ---- launch 0: degree count (blocks 0..1023) + h = x@W (blocks 1024..3071) ----
__global__ void k_deg_xw(const void* p0, const void* p1, const void* p2, const void* p3,
                         int s0, int s1, int s2, int s3) {
    __shared__ float sW[D * D];
    Cls c = do_classify(p0, p1, p2, p3, s0, s1, s2, s3);
    int blk = blockIdx.x, tid = threadIdx.x;
    if (blk < 1024) {
        int e = blk * 256 + tid;
        if (e < c.E && e < EMAX) {
            int dst = fetch_idx(c.ei, c.E + e, c.ei32);
            if ((unsigned)dst < (unsigned)N_NODES) atomicAdd(&g_deg[dst], 1.0f);
        }
        return;
    }
    // x @ W part
    for (int i = tid; i < D * D; i += 256) sW[i] = c.W[i];
    __syncthreads();
    int row = (blk - 1024) * 4 + (tid >> 6);
    int col = tid & 63;
    const float* xr = c.x + row * D;
    float acc = 0.0f;
#pragma unroll
    for (int k = 0; k < D; k++) acc += xr[k] * sW[k * D + col];
    g_h[row * D + col] = acc;
}

// ---- launch 1: edge scatter (warp per edge) into zeroed g_agg ----
__global__ void k_scatter(const void* p0, const void* p1, const void* p2, const void* p3,
                          int s0, int s1, int s2, int s3) {
    Cls c = do_classify(p0, p1, p2, p3, s0, s1, s2, s3);
    int gw = (blockIdx.x * blockDim.x + threadIdx.x) >> 5;
    int lane = threadIdx.x & 31;
    if (gw >= c.E || gw >= EMAX) return;
    int src = fetch_idx(c.ei, gw, c.ei32);
    int dst = fetch_idx(c.ei, c.E + gw, c.ei32);
    if ((unsigned)src >= (unsigned)N_NODES) return;
    if ((unsigned)dst >= (unsigned)N_NODES) return;
    float norm = rsqrtf(g_deg[src] + 1.0f) * rsqrtf(g_deg[dst] + 1.0f);  // +1 self-loop
    float2 v = ((const float2*)(g_h + src * D))[lane];
    atomicAdd(&g_agg[dst * D + lane * 2],     norm * v.x);
    atomicAdd(&g_agg[dst * D + lane * 2 + 1], norm * v.y);
}

// ---- launch 2: self-term + bias + relu + bf16 hi/lo split-pack ----
// A2=[hi|lo|hi], B2=[hi|hi|lo]
__global__ void k_pack(const void* p0, const void* p1, const void* p2, const void* p3,
                       int s0, int s1, int s2, int s3) {
    Cls c = do_classify(p0, p1, p2, p3, s0, s1, s2, s3);
    int idx = blockIdx.x * blockDim.x + threadIdx.x;
    if (idx >= N_NODES * D) return;
    int row = idx >> 6, col = idx & 63;
    float self = g_h[idx] / (g_deg[row] + 1.0f);   // dinv^2 * h
    float v = g_agg[idx] + self + c.b[col];
    v = v > 0.0f ? v : 0.0f;
    __nv_bfloat16 hi = __float2bfloat16(v);
    __nv_bfloat16 lo = __float2bfloat16(v - __bfloat162float(hi));
    __nv_bfloat16* a2 = g_A2 + row * KC;
    __nv_bfloat16* b2 = g_B2 + row * KC;
    a2[col] = hi; a2[col + 64] = lo; a2[col + 128] = hi;
    b2[col] = hi; b2[col + 64] = hi; b2[col + 128] = lo;
}

// ---- launch 3: C = A2 @ B2^T via mma.sync bf16, symmetric upper-tri tiles ----
#define ROW_BYTES (KC * 2)                  // 384
#define TILE_BYTES (128 * ROW_BYTES)        // 49152
#define SMEM_TOTAL (2 * TILE_BYTES)         // 98304
#define TSTRIDE 132
#define CLEAN_CTAS 2016
#define CLEAN_WORDS (N_NODES * D + N_NODES)         // 532480
#define WORDS_PER_CTA ((CLEAN_WORDS + CLEAN_CTAS - 1) / CLEAN_CTAS)   // 265

__device__ __forceinline__ uint32_t sw_off(int row, int chunk) {
    return (uint32_t)(row * ROW_BYTES + (((chunk & 24) | ((chunk & 7) ^ (row & 7))) << 4));
}

#define LDSM_X4(r0, r1, r2, r3, a) \
    asm volatile("ldmatrix.sync.aligned.m8n8.x4.shared.b16 {%0,%1,%2,%3}, [%4];" \
        : "=r"(r0), "=r"(r1), "=r"(r2), "=r"(r3) : "r"(a))

#define MMA_16816(d, a, b) \
    asm volatile("mma.sync.aligned.m16n8k16.row.col.f32.bf16.bf16.f32 " \
        "{%0,%1,%2,%3}, {%4,%5,%6,%7}, {%8,%9}, {%0,%1,%2,%3};" \
        : "+f"((d)[0]), "+f"((d)[1]), "+f"((d)[2]), "+f"((d)[3]) \
        : "r"((a)[0]), "r"((a)[1]), "r"((a)[2]), "r"((a)[3]), "r"((b)[0]), "r"((b)[1]))

#define CP_ASYNC_16(smem_addr, gptr) \
    asm volatile("cp.async.cg.shared.global [%0], [%1], 16;" :: "r"(smem_addr), "l"(gptr) : "memory")

__global__ void __launch_bounds__(256) k_gemm_mma(float* __restrict__ C) {
    int bi = blockIdx.y, bj = blockIdx.x;
    int tid = threadIdx.x;

    if (bj < bi) {
        // idle lower-triangle CTA: re-zero g_agg/g_deg for the next graph replay
        int cid = bi * (bi - 1) / 2 + bj;              // 0 .. 2015
        int w0 = cid * WORDS_PER_CTA;
        for (int k = tid; k < WORDS_PER_CTA; k += 256) {
            int w = w0 + k;
            if (w < N_NODES * D) g_agg[w] = 0.0f;
            else if (w < CLEAN_WORDS) g_deg[w - N_NODES * D] = 0.0f;
        }
        return;
    }

    extern __shared__ char smem[];
    char* sA = smem;
    char* sB = smem + TILE_BYTES;
    uint32_t sA_u = smem_u32(sA);
    uint32_t sB_u = smem_u32(sB);

    int wid = tid >> 5, lane = tid & 31;
    int warp_m = wid >> 1;         // 0..3 -> 32-row slice
    int warp_n = wid & 1;          // 0..1 -> 64-col slice

    const char* gA = (const char*)(g_A2 + bi * 128 * KC);
    const char* gB = (const char*)(g_B2 + bj * 128 * KC);
#pragma unroll
    for (int it = 0; it < 12; it++) {
        int q = it * 256 + tid;            // 0..3071
        int row = q / 24, chunk = q % 24;
        uint32_t off = sw_off(row, chunk);
        CP_ASYNC_16(sA_u + off, gA + q * 16);
        CP_ASYNC_16(sB_u + off, gB + q * 16);
    }
    asm volatile("cp.async.commit_group;" ::: "memory");
    asm volatile("cp.async.wait_group 0;" ::: "memory");
    __syncthreads();

    int a_row_in16 = (lane & 7) | (lane & 8);
    int a_csub = lane >> 4;
    int b_row_in16 = (lane & 7) | ((lane >> 1) & 8);
    int b_csub = (lane >> 3) & 1;

    float acc[2][8][4];
#pragma unroll
    for (int mi = 0; mi < 2; mi++)
#pragma unroll
        for (int ni = 0; ni < 8; ni++)
#pragma unroll
            for (int v = 0; v < 4; v++) acc[mi][ni][v] = 0.0f;

#pragma unroll
    for (int s = 0; s < 12; s++) {
        int kc = s * 2;

        uint32_t a[2][4];
#pragma unroll
        for (int mi = 0; mi < 2; mi++) {
            int row = warp_m * 32 + mi * 16 + a_row_in16;
            uint32_t addr = sA_u + sw_off(row, kc + a_csub);
            LDSM_X4(a[mi][0], a[mi][1], a[mi][2], a[mi][3], addr);
        }

        uint32_t b[4][4];
#pragma unroll
        for (int nt = 0; nt < 4; nt++) {
            int row = warp_n * 64 + nt * 16 + b_row_in16;
            uint32_t addr = sB_u + sw_off(row, kc + b_csub);
            LDSM_X4(b[nt][0], b[nt][1], b[nt][2], b[nt][3], addr);
        }

#pragma unroll
        for (int mi = 0; mi < 2; mi++)
#pragma unroll
            for (int ni = 0; ni < 8; ni++) {
                uint32_t bb[2];
                bb[0] = b[ni >> 1][(ni & 1) * 2];
                bb[1] = b[ni >> 1][(ni & 1) * 2 + 1];
                MMA_16816(acc[mi][ni], a[mi], bb);
            }
    }

    // ---- epilogue 1: direct store of C[bi, bj] ----
    int gr = lane >> 2, gc = (lane & 3) * 2;
#pragma unroll
    for (int mi = 0; mi < 2; mi++) {
        int row0 = bi * 128 + warp_m * 32 + mi * 16 + gr;
#pragma unroll
        for (int ni = 0; ni < 8; ni++) {
            int col = bj * 128 + warp_n * 64 + ni * 8 + gc;
            float* pp0 = C + (long long)row0 * NT + col;
            float* pp1 = pp0 + 8LL * NT;
            *(float2*)pp0 = make_float2(acc[mi][ni][0], acc[mi][ni][1]);
            *(float2*)pp1 = make_float2(acc[mi][ni][2], acc[mi][ni][3]);
        }
    }

    // ---- epilogue 2: transposed store of C[bj, bi] via smem staging ----
    if (bi == bj) return;
    __syncthreads();
    float* sT = (float*)smem;   // 128 x TSTRIDE floats = 67584 B
#pragma unroll
    for (int mi = 0; mi < 2; mi++) {
        int lr = warp_m * 32 + mi * 16 + gr;
#pragma unroll
        for (int ni = 0; ni < 8; ni++) {
            int lc = warp_n * 64 + ni * 8 + gc;
            sT[lc * TSTRIDE + lr]           = acc[mi][ni][0];
            sT[(lc + 1) * TSTRIDE + lr]     = acc[mi][ni][1];
            sT[lc * TSTRIDE + lr + 8]       = acc[mi][ni][2];
            sT[(lc + 1) * TSTRIDE + lr + 8] = acc[mi][ni][3];
        }
    }
    __syncthreads();
    int half = tid >> 7;
    int r = tid & 127;
    const float* srow = sT + r * TSTRIDE + half * 64;
    float* drow = C + (long long)(bj * 128 + r) * NT + bi * 128 + half * 64;
#pragma unroll
    for (int k = 0; k < 16; k++) {
        float4 v = *(const float4*)(srow + k * 4);
        *(float4*)(drow + k * 4) = v;
    }
}

extern "C" void kernel_launch(void* const* d_in, const int* in_sizes, int n_in,
                              void* d_out, int out_size) {
    float* out = (float*)d_out;

    const void* p0 = n_in > 0 ? d_in[0] : nullptr;
    const void* p1 = n_in > 1 ? d_in[1] : nullptr;
    const void* p2 = n_in > 2 ? d_in[2] : nullptr;
    const void* p3 = n_in > 3 ? d_in[3] : nullptr;
    int s0 = n_in > 0 ? in_sizes[0] : 0;
    int s1 = n_in > 1 ? in_sizes[1] : 0;
    int s2 = n_in > 2 ? in_sizes[2] : 0;
    int s3 = n_in > 3 ? in_sizes[3] : 0;

    static bool attr_set = false;
    if (!attr_set) {
        cudaFuncSetAttribute(k_gemm_mma, cudaFuncAttributeMaxDynamicSharedMemorySize, SMEM_TOTAL);
        attr_set = true;
    }

    // launch 0: degree count (1024 blocks) + x@W (2048 blocks)
    k_deg_xw<<<3072, 256>>>(p0, p1, p2, p3, s0, s1, s2, s3);
    // launch 1: edge scatter, warp per edge
    k_scatter<<<(EMAX + 7) / 8, 256>>>(p0, p1, p2, p3, s0, s1, s2, s3);
    // launch 2: self term + bias + relu + split-pack
    k_pack<<<(N_NODES * D + 255) / 256, 256>>>(p0, p1, p2, p3, s0, s1, s2, s3);
    // launch 3: GEMM (profiled at ncu skip-index 3)
    dim3 grid(NT / 128, NT / 128);
    k_gemm_mma<<<grid, 256, SMEM_TOTAL>>>(out);
}

// round 8
// speedup vs baseline: 1.4721x; 1.4721x over previous
#include <cuda_runtime.h>
#include <cuda_bf16.h>
#include <math.h>
#include <stdint.h>

#define N_NODES 8192
#define D 64
#define NT 8192
#define KC 192            // packed K: [hi | lo | hi] / [hi | hi | lo]
#define EMAX 262144

// ---------------- scratch (no allocations allowed) ----------------
// Invariant: g_deg and g_agg are ZERO at entry to kernel_launch (zero-init at
// load; re-zeroed by the GEMM's idle lower-triangle CTAs every call).
__device__ float g_deg[N_NODES];
__device__ float g_h[N_NODES * D];     // x @ W
__device__ float g_agg[N_NODES * D];   // neighbor-sum (excl. self term)
__device__ __nv_bfloat16 g_A2[N_NODES * KC];
__device__ __nv_bfloat16 g_B2[N_NODES * KC];

struct Cls {
    const float* x;
    const void*  ei;
    const float* W;
    const float* b;
    int E;
    int ei32;
};

// Published by launch 0 (block 0) for later launches.
__device__ const float* gp_x;
__device__ const void*  gp_ei;
__device__ const float* gp_W;
__device__ const float* gp_b;
__device__ int          g_E;
__device__ int          g_ei32;

// Cheap content test: 8 independent samples. float32 N(0,1) bit patterns can
// never read back as integers in [0, N_NODES) for all samples.
__device__ __forceinline__ bool rok64(const long long* p, int n) {
    int st = n >> 3;
    long long v[8];
#pragma unroll
    for (int k = 0; k < 8; k++) v[k] = p[k * st];
    bool ok = true;
#pragma unroll
    for (int k = 0; k < 8; k++) ok &= (v[k] >= 0 && v[k] < N_NODES);
    return ok;
}
__device__ __forceinline__ bool rok32(const int* p, int n) {
    int st = n >> 3;
    int v[8];
#pragma unroll
    for (int k = 0; k < 8; k++) v[k] = p[k * st];
    bool ok = true;
#pragma unroll
    for (int k = 0; k < 8; k++) ok &= (v[k] >= 0 && v[k] < N_NODES);
    return ok;
}

__device__ Cls do_classify(const void* p0, const void* p1, const void* p2, const void* p3,
                           int s0, int s1, int s2, int s3) {
    Cls c; c.x = nullptr; c.ei = nullptr; c.W = nullptr; c.b = nullptr; c.E = 0; c.ei32 = 1;
    const void* ps[4] = {p0, p1, p2, p3};
    int ss[4] = {s0, s1, s2, s3};
    int big[2]; int nb = 0;
#pragma unroll
    for (int j = 0; j < 4; j++) {
        if (ss[j] == D) c.b = (const float*)ps[j];
        else if (ss[j] == D * D) c.W = (const float*)ps[j];
        else if (nb < 2) big[nb++] = j;
    }
#pragma unroll
    for (int k = 0; k < 2; k++) {
        const void* cand = ps[big[k]];
        int n = ss[big[k]];
        const void* other = ps[big[1 - k]];
        if (rok64((const long long*)cand, n)) {
            c.ei = cand; c.ei32 = 0; c.E = n / 2; c.x = (const float*)other; return c;
        }
        if (rok32((const int*)cand, n)) {
            c.ei = cand; c.ei32 = 1; c.E = n / 2; c.x = (const float*)other; return c;
        }
    }
    c.ei = ps[big[1]]; c.ei32 = 1; c.E = ss[big[1]] / 2;
    c.x = (const float*)ps[big[0]];
    return c;
}

__device__ __forceinline__ int fetch_idx(const void* ei, int i, int ei32) {
    if (ei32) return ((const int*)ei)[i];
    return (int)((const long long*)ei)[i];
}

__device__ __forceinline__ uint32_t smem_u32(const void* p) {
    uint32_t a;
    asm("{ .reg .u64 t; cvta.to.shared.u64 t, %1; cvt.u32.u64 %0, t; }" : "=r"(a) : "l"(p));
    return a;
}

// ---- launch 0: classify+publish, degree count (blocks 0..1023), x@W (1024..3071) ----
__global__ void k_deg_xw(const void* p0, const void* p1, const void* p2, const void* p3,
                         int s0, int s1, int s2, int s3) {
    __shared__ float sW[D * D];
    Cls c = do_classify(p0, p1, p2, p3, s0, s1, s2, s3);
    int blk = blockIdx.x, tid = threadIdx.x;
    if (blk == 0 && tid == 0) {   // publish for later launches
        gp_x = c.x; gp_ei = c.ei; gp_W = c.W; gp_b = c.b; g_E = c.E; g_ei32 = c.ei32;
        __threadfence();
    }
    if (blk < 1024) {
        int e = blk * 256 + tid;
        if (e < c.E && e < EMAX) {
            int dst = fetch_idx(c.ei, c.E + e, c.ei32);
            if ((unsigned)dst < (unsigned)N_NODES) atomicAdd(&g_deg[dst], 1.0f);
        }
        return;
    }
    for (int i = tid; i < D * D; i += 256) sW[i] = c.W[i];
    __syncthreads();
    int row = (blk - 1024) * 4 + (tid >> 6);
    int col = tid & 63;
    const float* xr = c.x + row * D;
    float acc = 0.0f;
#pragma unroll
    for (int k = 0; k < D; k++) acc += xr[k] * sW[k * D + col];
    g_h[row * D + col] = acc;
}

// ---- launch 1: edge scatter (warp per edge) into zeroed g_agg ----
__global__ void k_scatter() {
    const void* ei = gp_ei;
    int E = g_E, ei32 = g_ei32;
    int gw = (blockIdx.x * blockDim.x + threadIdx.x) >> 5;
    int lane = threadIdx.x & 31;
    if (gw >= E || gw >= EMAX) return;
    int src = fetch_idx(ei, gw, ei32);
    int dst = fetch_idx(ei, E + gw, ei32);
    if ((unsigned)src >= (unsigned)N_NODES) return;
    if ((unsigned)dst >= (unsigned)N_NODES) return;
    float norm = rsqrtf(g_deg[src] + 1.0f) * rsqrtf(g_deg[dst] + 1.0f);  // +1 self-loop
    float2 v = ((const float2*)(g_h + src * D))[lane];
    atomicAdd(&g_agg[dst * D + lane * 2],     norm * v.x);
    atomicAdd(&g_agg[dst * D + lane * 2 + 1], norm * v.y);
}

// ---- launch 2: self-term + bias + relu + bf16 hi/lo split-pack ----
__global__ void k_pack() {
    const float* __restrict__ b = gp_b;
    int idx = blockIdx.x * blockDim.x + threadIdx.x;
    if (idx >= N_NODES * D) return;
    int row = idx >> 6, col = idx & 63;
    float self = g_h[idx] / (g_deg[row] + 1.0f);   // dinv^2 * h
    float v = g_agg[idx] + self + b[col];
    v = v > 0.0f ? v : 0.0f;
    __nv_bfloat16 hi = __float2bfloat16(v);
    __nv_bfloat16 lo = __float2bfloat16(v - __bfloat162float(hi));
    __nv_bfloat16* a2 = g_A2 + row * KC;
    __nv_bfloat16* b2 = g_B2 + row * KC;
    a2[col] = hi; a2[col + 64] = lo; a2[col + 128] = hi;
    b2[col] = hi; b2[col + 64] = hi; b2[col + 128] = lo;
}

// ---- launch 3: C = A2 @ B2^T via mma.sync bf16, symmetric upper-tri tiles ----
#define ROW_BYTES (KC * 2)                  // 384
#define TILE_BYTES (128 * ROW_BYTES)        // 49152
#define SMEM_TOTAL (2 * TILE_BYTES)         // 98304
#define TSTRIDE 132
#define CLEAN_CTAS 2016
#define CLEAN_WORDS (N_NODES * D + N_NODES)
#define WORDS_PER_CTA ((CLEAN_WORDS + CLEAN_CTAS - 1) / CLEAN_CTAS)

__device__ __forceinline__ uint32_t sw_off(int row, int chunk) {
    return (uint32_t)(row * ROW_BYTES + (((chunk & 24) | ((chunk & 7) ^ (row & 7))) << 4));
}

#define LDSM_X4(r0, r1, r2, r3, a) \
    asm volatile("ldmatrix.sync.aligned.m8n8.x4.shared.b16 {%0,%1,%2,%3}, [%4];" \
        : "=r"(r0), "=r"(r1), "=r"(r2), "=r"(r3) : "r"(a))

#define MMA_16816(d, a, b) \
    asm volatile("mma.sync.aligned.m16n8k16.row.col.f32.bf16.bf16.f32 " \
        "{%0,%1,%2,%3}, {%4,%5,%6,%7}, {%8,%9}, {%0,%1,%2,%3};" \
        : "+f"((d)[0]), "+f"((d)[1]), "+f"((d)[2]), "+f"((d)[3]) \
        : "r"((a)[0]), "r"((a)[1]), "r"((a)[2]), "r"((a)[3]), "r"((b)[0]), "r"((b)[1]))

#define CP_ASYNC_16(smem_addr, gptr) \
    asm volatile("cp.async.cg.shared.global [%0], [%1], 16;" :: "r"(smem_addr), "l"(gptr) : "memory")

__global__ void __launch_bounds__(256) k_gemm_mma(float* __restrict__ C) {
    int bi = blockIdx.y, bj = blockIdx.x;
    int tid = threadIdx.x;

    if (bj < bi) {
        // idle lower-triangle CTA: re-zero g_agg/g_deg for the next graph replay
        int cid = bi * (bi - 1) / 2 + bj;
        int w0 = cid * WORDS_PER_CTA;
        for (int k = tid; k < WORDS_PER_CTA; k += 256) {
            int w = w0 + k;
            if (w < N_NODES * D) g_agg[w] = 0.0f;
            else if (w < CLEAN_WORDS) g_deg[w - N_NODES * D] = 0.0f;
        }
        return;
    }

    extern __shared__ char smem[];
    char* sA = smem;
    char* sB = smem + TILE_BYTES;
    uint32_t sA_u = smem_u32(sA);
    uint32_t sB_u = smem_u32(sB);

    int wid = tid >> 5, lane = tid & 31;
    int warp_m = wid >> 1;
    int warp_n = wid & 1;

    const char* gA = (const char*)(g_A2 + bi * 128 * KC);
    const char* gB = (const char*)(g_B2 + bj * 128 * KC);

    // Two commit groups by K-half (chunks 0-11, 12-23); 1536 chunks per half
    // per tile, 6 iters x 256 threads each.
#pragma unroll
    for (int h = 0; h < 2; h++) {
#pragma unroll
        for (int it = 0; it < 6; it++) {
            int q = it * 256 + tid;               // 0..1535
            int row = q / 12, chunk = h * 12 + q % 12;
            uint32_t off = sw_off(row, chunk);
            const char* srcA = gA + row * ROW_BYTES + chunk * 16;
            const char* srcB = gB + row * ROW_BYTES + chunk * 16;
            CP_ASYNC_16(sA_u + off, srcA);
            CP_ASYNC_16(sB_u + off, srcB);
        }
        asm volatile("cp.async.commit_group;" ::: "memory");
    }

    int a_row_in16 = (lane & 7) | (lane & 8);
    int a_csub = lane >> 4;
    int b_row_in16 = (lane & 7) | ((lane >> 1) & 8);
    int b_csub = (lane >> 3) & 1;

    float acc[2][8][4];
#pragma unroll
    for (int mi = 0; mi < 2; mi++)
#pragma unroll
        for (int ni = 0; ni < 8; ni++)
#pragma unroll
            for (int v = 0; v < 4; v++) acc[mi][ni][v] = 0.0f;

    // half 0 ready (1 group pending), compute s=0..5; then all ready, s=6..11
    asm volatile("cp.async.wait_group 1;" ::: "memory");
    __syncthreads();

#pragma unroll
    for (int half = 0; half < 2; half++) {
        if (half == 1) {
            asm volatile("cp.async.wait_group 0;" ::: "memory");
            __syncthreads();
        }
#pragma unroll
        for (int s6 = 0; s6 < 6; s6++) {
            int kc = (half * 6 + s6) * 2;

            uint32_t a[2][4];
#pragma unroll
            for (int mi = 0; mi < 2; mi++) {
                int row = warp_m * 32 + mi * 16 + a_row_in16;
                uint32_t addr = sA_u + sw_off(row, kc + a_csub);
                LDSM_X4(a[mi][0], a[mi][1], a[mi][2], a[mi][3], addr);
            }

            uint32_t b[4][4];
#pragma unroll
            for (int nt = 0; nt < 4; nt++) {
                int row = warp_n * 64 + nt * 16 + b_row_in16;
                uint32_t addr = sB_u + sw_off(row, kc + b_csub);
                LDSM_X4(b[nt][0], b[nt][1], b[nt][2], b[nt][3], addr);
            }

#pragma unroll
            for (int mi = 0; mi < 2; mi++)
#pragma unroll
                for (int ni = 0; ni < 8; ni++) {
                    uint32_t bb[2];
                    bb[0] = b[ni >> 1][(ni & 1) * 2];
                    bb[1] = b[ni >> 1][(ni & 1) * 2 + 1];
                    MMA_16816(acc[mi][ni], a[mi], bb);
                }
        }
    }

    // ---- epilogue 1: direct store of C[bi, bj] ----
    int gr = lane >> 2, gc = (lane & 3) * 2;
#pragma unroll
    for (int mi = 0; mi < 2; mi++) {
        int row0 = bi * 128 + warp_m * 32 + mi * 16 + gr;
#pragma unroll
        for (int ni = 0; ni < 8; ni++) {
            int col = bj * 128 + warp_n * 64 + ni * 8 + gc;
            float* pp0 = C + (long long)row0 * NT + col;
            float* pp1 = pp0 + 8LL * NT;
            *(float2*)pp0 = make_float2(acc[mi][ni][0], acc[mi][ni][1]);
            *(float2*)pp1 = make_float2(acc[mi][ni][2], acc[mi][ni][3]);
        }
    }

    // ---- epilogue 2: transposed store of C[bj, bi] via smem staging ----
    if (bi == bj) return;
    __syncthreads();
    float* sT = (float*)smem;
#pragma unroll
    for (int mi = 0; mi < 2; mi++) {
        int lr = warp_m * 32 + mi * 16 + gr;
#pragma unroll
        for (int ni = 0; ni < 8; ni++) {
            int lc = warp_n * 64 + ni * 8 + gc;
            sT[lc * TSTRIDE + lr]           = acc[mi][ni][0];
            sT[(lc + 1) * TSTRIDE + lr]     = acc[mi][ni][1];
            sT[lc * TSTRIDE + lr + 8]       = acc[mi][ni][2];
            sT[(lc + 1) * TSTRIDE + lr + 8] = acc[mi][ni][3];
        }
    }
    __syncthreads();
    int half = tid >> 7;
    int r = tid & 127;
    const float* srow = sT + r * TSTRIDE + half * 64;
    float* drow = C + (long long)(bj * 128 + r) * NT + bi * 128 + half * 64;
#pragma unroll
    for (int k = 0; k < 16; k++) {
        float4 v = *(const float4*)(srow + k * 4);
        *(float4*)(drow + k * 4) = v;
    }
}

extern "C" void kernel_launch(void* const* d_in, const int* in_sizes, int n_in,
                              void* d_out, int out_size) {
    float* out = (float*)d_out;

    const void* p0 = n_in > 0 ? d_in[0] : nullptr;
    const void* p1 = n_in > 1 ? d_in[1] : nullptr;
    const void* p2 = n_in > 2 ? d_in[2] : nullptr;
    const void* p3 = n_in > 3 ? d_in[3] : nullptr;
    int s0 = n_in > 0 ? in_sizes[0] : 0;
    int s1 = n_in > 1 ? in_sizes[1] : 0;
    int s2 = n_in > 2 ? in_sizes[2] : 0;
    int s3 = n_in > 3 ? in_sizes[3] : 0;

    static bool attr_set = false;
    if (!attr_set) {
        cudaFuncSetAttribute(k_gemm_mma, cudaFuncAttributeMaxDynamicSharedMemorySize, SMEM_TOTAL);
        attr_set = true;
    }

    // launch 0: classify/publish + degree count + x@W
    k_deg_xw<<<3072, 256>>>(p0, p1, p2, p3, s0, s1, s2, s3);
    // launch 1: edge scatter, warp per edge
    k_scatter<<<(EMAX + 7) / 8, 256>>>();
    // launch 2: self term + bias + relu + split-pack
    k_pack<<<(N_NODES * D + 255) / 256, 256>>>();
    // launch 3: GEMM (ncu captures this index)
    dim3 grid(NT / 128, NT / 128);
    k_gemm_mma<<<grid, 256, SMEM_TOTAL>>>(out);
}